// round 1
// baseline (speedup 1.0000x reference)
#include <cuda_runtime.h>
#include <cuda_bf16.h>

// LSTM: B=32768, T=28, IN=28, H=8, NC=10. Gate order i,j,f,o. Forget bias 1.0.
// One thread per batch element. Gates kept as 16 packed f32x2 accumulators
// (adjacent gate columns of W are contiguous -> natural pairs). Weights live in
// shared memory as 8-byte pairs, read via broadcast LDS.64. Packed FMAs use the
// Blackwell-only fma.rn.f32x2 (one issue = 2 fp32 FMAs), halving FFMA issue
// pressure versus scalar FFMA.

#define BTOT 32768
#define TSTEPS 28
#define INDIM 28
#define HID 8
#define NCLS 10

typedef unsigned long long u64;

__device__ __forceinline__ u64 pack2(float x) {
    u64 r; unsigned xi = __float_as_uint(x);
    asm("mov.b64 %0, {%1, %1};" : "=l"(r) : "r"(xi));
    return r;
}

__device__ __forceinline__ u64 fma2(u64 a, u64 b, u64 c) {
    u64 d;
    asm("fma.rn.f32x2 %0, %1, %2, %3;" : "=l"(d) : "l"(a), "l"(b), "l"(c));
    return d;
}

__device__ __forceinline__ void unpack2(u64 v, float& lo, float& hi) {
    unsigned a, b;
    asm("mov.b64 {%0, %1}, %2;" : "=r"(a), "=r"(b) : "l"(v));
    lo = __uint_as_float(a);
    hi = __uint_as_float(b);
}

__device__ __forceinline__ float sigf(float x) {
    // 1/(1+e^-x). __expf -> EX2-based, ~2 ulp. Saturates correctly at +-inf.
    float e = __expf(-x);
    return __fdividef(1.0f, 1.0f + e);
}

__device__ __forceinline__ float tanh_fast(float x) {
    // tanh(x) = 1 - 2/(e^{2x}+1). Overflow of e -> +1; underflow -> -1. Both correct.
    float e = __expf(2.0f * x);
    return 1.0f - __fdividef(2.0f, e + 1.0f);
}

__global__ __launch_bounds__(128)
void lstm_kernel(const float* __restrict__ x,
                 const float* __restrict__ W,      // [36, 32] row-major
                 const float* __restrict__ bias,   // [32]
                 const float* __restrict__ ow,     // [8, 10]
                 const float* __restrict__ ob,     // [10]
                 float* __restrict__ out)          // [B, 10]
{
    __shared__ u64  sW[(INDIM + HID) * 16];   // 36 rows x 16 f32x2 pairs
    __shared__ u64  sB[16];                   // bias pairs
    __shared__ float sOW[HID * NCLS];
    __shared__ float sOB[NCLS];

    const int tid = threadIdx.x;
    // W is 8-byte-aligned device allocation; reinterpret as pairs:
    // pair index i -> row k=i/16, gates (2g, 2g+1) with g=i%16. Exactly what we want.
    for (int i = tid; i < (INDIM + HID) * 16; i += 128)
        sW[i] = ((const u64*)W)[i];
    if (tid < 16)  sB[tid]  = ((const u64*)bias)[tid];
    if (tid < HID * NCLS) sOW[tid] = ow[tid];
    if (tid < NCLS)       sOB[tid] = ob[tid];
    __syncthreads();

    const int b = blockIdx.x * 128 + tid;
    const float4* xp = (const float4*)(x + (size_t)b * TSTEPS * INDIM);  // 112B rows, 16B aligned

    float c[HID], h[HID];
#pragma unroll
    for (int u = 0; u < HID; u++) { c[u] = 0.0f; h[u] = 0.0f; }

    for (int t = 0; t < TSTEPS; t++) {
        // Load this step's 28 inputs as 7 float4s (contiguous 112B per thread).
        float4 xv[7];
#pragma unroll
        for (int q = 0; q < 7; q++) xv[q] = xp[t * 7 + q];
        float xt[INDIM];
#pragma unroll
        for (int q = 0; q < 7; q++) {
            xt[4 * q + 0] = xv[q].x; xt[4 * q + 1] = xv[q].y;
            xt[4 * q + 2] = xv[q].z; xt[4 * q + 3] = xv[q].w;
        }

        // gates[2g,2g+1] as 16 packed accumulators, init with bias.
        u64 g[16];
#pragma unroll
        for (int p = 0; p < 16; p++) g[p] = sB[p];

#pragma unroll
        for (int k = 0; k < INDIM; k++) {
            u64 xx = pack2(xt[k]);
#pragma unroll
            for (int p = 0; p < 16; p++)
                g[p] = fma2(xx, sW[k * 16 + p], g[p]);
        }
#pragma unroll
        for (int k = 0; k < HID; k++) {
            u64 hh = pack2(h[k]);
#pragma unroll
            for (int p = 0; p < 16; p++)
                g[p] = fma2(hh, sW[(INDIM + k) * 16 + p], g[p]);
        }

        float ga[32];
#pragma unroll
        for (int p = 0; p < 16; p++) unpack2(g[p], ga[2 * p], ga[2 * p + 1]);

        // cols 0..7 = i, 8..15 = j, 16..23 = f, 24..31 = o
#pragma unroll
        for (int u = 0; u < HID; u++) {
            float ig = sigf(ga[u]);
            float jt = tanh_fast(ga[8 + u]);
            float fg = sigf(ga[16 + u] + 1.0f);   // forget bias
            float og = sigf(ga[24 + u]);
            c[u] = c[u] * fg + ig * jt;
            h[u] = tanh_fast(c[u]) * og;
        }
    }

    // Output projection: logits = h @ ow + ob
    float* op = out + (size_t)b * NCLS;
#pragma unroll
    for (int n = 0; n < NCLS; n++) {
        float acc = sOB[n];
#pragma unroll
        for (int u = 0; u < HID; u++) acc += h[u] * sOW[u * NCLS + n];
        op[n] = acc;
    }
}

extern "C" void kernel_launch(void* const* d_in, const int* in_sizes, int n_in,
                              void* d_out, int out_size) {
    const float* x    = (const float*)d_in[0];
    const float* W    = (const float*)d_in[1];
    const float* bl   = (const float*)d_in[2];
    const float* ow   = (const float*)d_in[3];
    const float* ob   = (const float*)d_in[4];
    float* out = (float*)d_out;

    lstm_kernel<<<BTOT / 128, 128>>>(x, W, bl, ow, ob, out);
}

// round 6
// speedup vs baseline: 1.0302x; 1.0302x over previous
#include <cuda_runtime.h>
#include <cuda_bf16.h>

// LSTM: B=32768, T=28, IN=28, H=8, NC=10. Gate order i,j,f,o. Forget bias 1.0.
// One thread per batch element.
//  - Gates: 16 packed f32x2 accumulators (fma.rn.f32x2 = 2 FMAs/issue).
//  - Weights: shared memory, read as ulonglong2 (LDS.128 broadcast = 2 f32x2 operands).
//  - x streamed one float4 at a time (no long-lived arrays -> no spills).
//  - Activations: EXACT path (__expf + __fdividef), rel_err 1.2e-7 proven in R1.
// R4/R5 bug fixed: sOW has 80 elements but BLK=64 -> `if (tid < 80)` left
// sOW[64..79] uninitialized. All shared init loops are now strided.

#define BTOT 32768
#define TSTEPS 28
#define INDIM 28
#define HID 8
#define NCLS 10
#define BLK 64

typedef unsigned long long u64;

__device__ __forceinline__ u64 pack2(float x) {
    u64 r; unsigned xi = __float_as_uint(x);
    asm("mov.b64 %0, {%1, %1};" : "=l"(r) : "r"(xi));
    return r;
}

__device__ __forceinline__ u64 fma2(u64 a, u64 b, u64 c) {
    u64 d;
    asm("fma.rn.f32x2 %0, %1, %2, %3;" : "=l"(d) : "l"(a), "l"(b), "l"(c));
    return d;
}

__device__ __forceinline__ void unpack2(u64 v, float& lo, float& hi) {
    unsigned a, b;
    asm("mov.b64 {%0, %1}, %2;" : "=r"(a), "=r"(b) : "l"(v));
    lo = __uint_as_float(a);
    hi = __uint_as_float(b);
}

__device__ __forceinline__ float sigf(float x) {
    float e = __expf(-x);
    return __fdividef(1.0f, 1.0f + e);
}

__device__ __forceinline__ float tanh_exact(float x) {
    // tanh(x) = 1 - 2/(e^{2x}+1). Overflow of e -> +1; underflow -> -1. Both correct.
    float e = __expf(2.0f * x);
    return 1.0f - __fdividef(2.0f, e + 1.0f);
}

__global__ __launch_bounds__(BLK, 4)
void lstm_kernel(const float* __restrict__ x,
                 const float* __restrict__ W,      // [36, 32] row-major
                 const float* __restrict__ bias,   // [32]
                 const float* __restrict__ ow,     // [8, 10]
                 const float* __restrict__ ob,     // [10]
                 float* __restrict__ out)          // [B, 10]
{
    // Row k occupies sW2[k*8 .. k*8+7]; quad q holds gate columns 4q..4q+3.
    __shared__ ulonglong2 sW2[(INDIM + HID) * 8];   // 36 * 128B
    __shared__ ulonglong2 sB2[8];                   // bias as 8 quads
    __shared__ float sOW[HID * NCLS];
    __shared__ float sOB[NCLS];

    const int tid = threadIdx.x;
    {
        const u64* gW = (const u64*)W;
        u64* sw = (u64*)sW2;
        for (int i = tid; i < (INDIM + HID) * 16; i += BLK) sw[i] = gW[i];
        for (int i = tid; i < 16; i += BLK)         ((u64*)sB2)[i] = ((const u64*)bias)[i];
        for (int i = tid; i < HID * NCLS; i += BLK) sOW[i] = ow[i];   // 80 elems: MUST stride
        for (int i = tid; i < NCLS; i += BLK)       sOB[i] = ob[i];
    }
    __syncthreads();

    const int b = blockIdx.x * BLK + tid;
    const float4* xp = (const float4*)(x + (size_t)b * TSTEPS * INDIM);  // 7 float4 per step

    float c[HID], h[HID];
#pragma unroll
    for (int u = 0; u < HID; u++) { c[u] = 0.0f; h[u] = 0.0f; }

    for (int t = 0; t < TSTEPS; t++) {
        // init gate accumulators with bias
        u64 g[16];
#pragma unroll
        for (int q = 0; q < 8; q++) {
            ulonglong2 bq = sB2[q];
            g[2 * q] = bq.x; g[2 * q + 1] = bq.y;
        }

        // x contribution: stream 7 float4 chunks, consume immediately
#pragma unroll
        for (int ch = 0; ch < 7; ch++) {
            float4 xv = xp[t * 7 + ch];
#pragma unroll
            for (int j = 0; j < 4; j++) {
                float xs = (j == 0) ? xv.x : (j == 1) ? xv.y : (j == 2) ? xv.z : xv.w;
                u64 xx = pack2(xs);
                const int k = 4 * ch + j;
#pragma unroll
                for (int q = 0; q < 8; q++) {
                    ulonglong2 w = sW2[k * 8 + q];
                    g[2 * q]     = fma2(xx, w.x, g[2 * q]);
                    g[2 * q + 1] = fma2(xx, w.y, g[2 * q + 1]);
                }
            }
        }

        // h contribution
#pragma unroll
        for (int k = 0; k < HID; k++) {
            u64 hh = pack2(h[k]);
#pragma unroll
            for (int q = 0; q < 8; q++) {
                ulonglong2 w = sW2[(INDIM + k) * 8 + q];
                g[2 * q]     = fma2(hh, w.x, g[2 * q]);
                g[2 * q + 1] = fma2(hh, w.y, g[2 * q + 1]);
            }
        }

        // activations: cols 0..7 = i, 8..15 = j, 16..23 = f, 24..31 = o
        // pair v covers hidden units u=2v, 2v+1.
#pragma unroll
        for (int v = 0; v < 4; v++) {
            float i0, i1, j0, j1, f0, f1, o0, o1;
            unpack2(g[v],      i0, i1);
            unpack2(g[4 + v],  j0, j1);
            unpack2(g[8 + v],  f0, f1);
            unpack2(g[12 + v], o0, o1);
#pragma unroll
            for (int s = 0; s < 2; s++) {
                const int u = 2 * v + s;
                float iv = s ? i1 : i0, jv = s ? j1 : j0;
                float fv = s ? f1 : f0, ov = s ? o1 : o0;
                float ig = sigf(iv);
                float jt = tanh_exact(jv);
                float fg = sigf(fv + 1.0f);   // forget bias
                float og = sigf(ov);
                c[u] = c[u] * fg + ig * jt;
                h[u] = tanh_exact(c[u]) * og;
            }
        }
    }

    // Output projection: logits = h @ ow + ob
    float* op = out + (size_t)b * NCLS;
#pragma unroll
    for (int n = 0; n < NCLS; n++) {
        float acc = sOB[n];
#pragma unroll
        for (int u = 0; u < HID; u++) acc += h[u] * sOW[u * NCLS + n];
        op[n] = acc;
    }
}

extern "C" void kernel_launch(void* const* d_in, const int* in_sizes, int n_in,
                              void* d_out, int out_size) {
    const float* x  = (const float*)d_in[0];
    const float* W  = (const float*)d_in[1];
    const float* bl = (const float*)d_in[2];
    const float* ow = (const float*)d_in[3];
    const float* ob = (const float*)d_in[4];
    float* out = (float*)d_out;

    lstm_kernel<<<BTOT / BLK, BLK>>>(x, W, bl, ow, ob, out);
}

// round 7
// speedup vs baseline: 1.0323x; 1.0021x over previous
#include <cuda_runtime.h>
#include <cuda_bf16.h>

// LSTM: B=32768, T=28, IN=28, H=8, NC=10. Gate order i,j,f,o. Forget bias 1.0.
// One thread per batch element.
//  - Gates: 16 packed f32x2 accumulators (fma.rn.f32x2 = 2 FMAs/issue).
//  - Weights: shared memory, read as ulonglong2 (LDS.128 broadcast = 2 f32x2 operands).
//  - x streamed one float4 at a time.
//  - Activations: EXACT path (__expf + __fdividef), rel_err 1.19e-7 proven.
//  - R7 fix: #pragma unroll 1 on the time loop. Full unroll of the 28-step
//    body stretched live ranges across steps -> 255 regs + ~3.4 GB of
//    local-memory spill traffic (the real cause of R1/R6's 670-690 us).

#define BTOT 32768
#define TSTEPS 28
#define INDIM 28
#define HID 8
#define NCLS 10
#define BLK 64

typedef unsigned long long u64;

__device__ __forceinline__ u64 pack2(float x) {
    u64 r; unsigned xi = __float_as_uint(x);
    asm("mov.b64 %0, {%1, %1};" : "=l"(r) : "r"(xi));
    return r;
}

__device__ __forceinline__ u64 fma2(u64 a, u64 b, u64 c) {
    u64 d;
    asm("fma.rn.f32x2 %0, %1, %2, %3;" : "=l"(d) : "l"(a), "l"(b), "l"(c));
    return d;
}

__device__ __forceinline__ void unpack2(u64 v, float& lo, float& hi) {
    unsigned a, b;
    asm("mov.b64 {%0, %1}, %2;" : "=r"(a), "=r"(b) : "l"(v));
    lo = __uint_as_float(a);
    hi = __uint_as_float(b);
}

__device__ __forceinline__ float sigf(float x) {
    float e = __expf(-x);
    return __fdividef(1.0f, 1.0f + e);
}

__device__ __forceinline__ float tanh_exact(float x) {
    // tanh(x) = 1 - 2/(e^{2x}+1). Overflow of e -> +1; underflow -> -1. Both correct.
    float e = __expf(2.0f * x);
    return 1.0f - __fdividef(2.0f, e + 1.0f);
}

__global__ __launch_bounds__(BLK, 4)
void lstm_kernel(const float* __restrict__ x,
                 const float* __restrict__ W,      // [36, 32] row-major
                 const float* __restrict__ bias,   // [32]
                 const float* __restrict__ ow,     // [8, 10]
                 const float* __restrict__ ob,     // [10]
                 float* __restrict__ out)          // [B, 10]
{
    // Row k occupies sW2[k*8 .. k*8+7]; quad q holds gate columns 4q..4q+3.
    __shared__ ulonglong2 sW2[(INDIM + HID) * 8];   // 36 * 128B
    __shared__ ulonglong2 sB2[8];                   // bias as 8 quads
    __shared__ float sOW[HID * NCLS];
    __shared__ float sOB[NCLS];

    const int tid = threadIdx.x;
    {
        const u64* gW = (const u64*)W;
        u64* sw = (u64*)sW2;
        for (int i = tid; i < (INDIM + HID) * 16; i += BLK) sw[i] = gW[i];
        for (int i = tid; i < 16; i += BLK)         ((u64*)sB2)[i] = ((const u64*)bias)[i];
        for (int i = tid; i < HID * NCLS; i += BLK) sOW[i] = ow[i];   // 80 elems: strided
        for (int i = tid; i < NCLS; i += BLK)       sOB[i] = ob[i];
    }
    __syncthreads();

    const int b = blockIdx.x * BLK + tid;
    const float4* xp = (const float4*)(x + (size_t)b * TSTEPS * INDIM);  // 7 float4 per step

    float c[HID], h[HID];
#pragma unroll
    for (int u = 0; u < HID; u++) { c[u] = 0.0f; h[u] = 0.0f; }

#pragma unroll 1   // CRITICAL: full unroll of 28 steps caused 255-reg spill storm
    for (int t = 0; t < TSTEPS; t++) {
        // init gate accumulators with bias
        u64 g[16];
#pragma unroll
        for (int q = 0; q < 8; q++) {
            ulonglong2 bq = sB2[q];
            g[2 * q] = bq.x; g[2 * q + 1] = bq.y;
        }

        // x contribution: stream 7 float4 chunks, consume immediately
#pragma unroll
        for (int ch = 0; ch < 7; ch++) {
            float4 xv = xp[t * 7 + ch];
#pragma unroll
            for (int j = 0; j < 4; j++) {
                float xs = (j == 0) ? xv.x : (j == 1) ? xv.y : (j == 2) ? xv.z : xv.w;
                u64 xx = pack2(xs);
                const int k = 4 * ch + j;
#pragma unroll
                for (int q = 0; q < 8; q++) {
                    ulonglong2 w = sW2[k * 8 + q];
                    g[2 * q]     = fma2(xx, w.x, g[2 * q]);
                    g[2 * q + 1] = fma2(xx, w.y, g[2 * q + 1]);
                }
            }
        }

        // h contribution
#pragma unroll
        for (int k = 0; k < HID; k++) {
            u64 hh = pack2(h[k]);
#pragma unroll
            for (int q = 0; q < 8; q++) {
                ulonglong2 w = sW2[(INDIM + k) * 8 + q];
                g[2 * q]     = fma2(hh, w.x, g[2 * q]);
                g[2 * q + 1] = fma2(hh, w.y, g[2 * q + 1]);
            }
        }

        // activations: cols 0..7 = i, 8..15 = j, 16..23 = f, 24..31 = o
        // pair v covers hidden units u=2v, 2v+1.
#pragma unroll
        for (int v = 0; v < 4; v++) {
            float i0, i1, j0, j1, f0, f1, o0, o1;
            unpack2(g[v],      i0, i1);
            unpack2(g[4 + v],  j0, j1);
            unpack2(g[8 + v],  f0, f1);
            unpack2(g[12 + v], o0, o1);
#pragma unroll
            for (int s = 0; s < 2; s++) {
                const int u = 2 * v + s;
                float iv = s ? i1 : i0, jv = s ? j1 : j0;
                float fv = s ? f1 : f0, ov = s ? o1 : o0;
                float ig = sigf(iv);
                float jt = tanh_exact(jv);
                float fg = sigf(fv + 1.0f);   // forget bias
                float og = sigf(ov);
                c[u] = c[u] * fg + ig * jt;
                h[u] = tanh_exact(c[u]) * og;
            }
        }
    }

    // Output projection: logits = h @ ow + ob
    float* op = out + (size_t)b * NCLS;
#pragma unroll
    for (int n = 0; n < NCLS; n++) {
        float acc = sOB[n];
#pragma unroll
        for (int u = 0; u < HID; u++) acc += h[u] * sOW[u * NCLS + n];
        op[n] = acc;
    }
}

extern "C" void kernel_launch(void* const* d_in, const int* in_sizes, int n_in,
                              void* d_out, int out_size) {
    const float* x  = (const float*)d_in[0];
    const float* W  = (const float*)d_in[1];
    const float* bl = (const float*)d_in[2];
    const float* ow = (const float*)d_in[3];
    const float* ob = (const float*)d_in[4];
    float* out = (float*)d_out;

    lstm_kernel<<<BTOT / BLK, BLK>>>(x, W, bl, ow, ob, out);
}

// round 8
// speedup vs baseline: 6.2189x; 6.0245x over previous
#include <cuda_runtime.h>
#include <cuda_bf16.h>

// LSTM: B=32768, T=28, IN=28, H=8, NC=10. Gate order i,j,f,o. Forget bias 1.0.
// One thread per batch element.
// R8: the 255-reg/spill cause was the single-step straight-line region
// (288 LDS.128 + 576 FFMA2) letting ptxas hoist loads until it spilled.
// Each step is now a #pragma unroll 1 loop over 9 segments (7 x-chunks + 2
// h-chunks packed as float4), each a bounded 32-LDS/64-FFMA2 window, with the
// next segment's operand software-pipelined one iteration ahead.

#define BTOT 32768
#define TSTEPS 28
#define INDIM 28
#define HID 8
#define NCLS 10
#define BLK 64

typedef unsigned long long u64;

__device__ __forceinline__ u64 pack2(float x) {
    u64 r; unsigned xi = __float_as_uint(x);
    asm("mov.b64 %0, {%1, %1};" : "=l"(r) : "r"(xi));
    return r;
}

__device__ __forceinline__ u64 fma2(u64 a, u64 b, u64 c) {
    u64 d;
    asm("fma.rn.f32x2 %0, %1, %2, %3;" : "=l"(d) : "l"(a), "l"(b), "l"(c));
    return d;
}

__device__ __forceinline__ void unpack2(u64 v, float& lo, float& hi) {
    unsigned a, b;
    asm("mov.b64 {%0, %1}, %2;" : "=r"(a), "=r"(b) : "l"(v));
    lo = __uint_as_float(a);
    hi = __uint_as_float(b);
}

__device__ __forceinline__ float sigf(float x) {
    float e = __expf(-x);
    return __fdividef(1.0f, 1.0f + e);
}

__device__ __forceinline__ float tanh_exact(float x) {
    // tanh(x) = 1 - 2/(e^{2x}+1). Overflow of e -> +1; underflow -> -1. Both correct.
    float e = __expf(2.0f * x);
    return 1.0f - __fdividef(2.0f, e + 1.0f);
}

__global__ __launch_bounds__(BLK)
void lstm_kernel(const float* __restrict__ x,
                 const float* __restrict__ W,      // [36, 32] row-major
                 const float* __restrict__ bias,   // [32]
                 const float* __restrict__ ow,     // [8, 10]
                 const float* __restrict__ ob,     // [10]
                 float* __restrict__ out)          // [B, 10]
{
    // Row k occupies sW2[k*8 .. k*8+7]; quad q holds gate columns 4q..4q+3.
    __shared__ ulonglong2 sW2[(INDIM + HID) * 8];   // 36 rows * 128B
    __shared__ ulonglong2 sB2[8];
    __shared__ float sOW[HID * NCLS];
    __shared__ float sOB[NCLS];

    const int tid = threadIdx.x;
    {
        const u64* gW = (const u64*)W;
        u64* sw = (u64*)sW2;
        for (int i = tid; i < (INDIM + HID) * 16; i += BLK) sw[i] = gW[i];
        for (int i = tid; i < 16; i += BLK)         ((u64*)sB2)[i] = ((const u64*)bias)[i];
        for (int i = tid; i < HID * NCLS; i += BLK) sOW[i] = ow[i];
        for (int i = tid; i < NCLS; i += BLK)       sOB[i] = ob[i];
    }
    __syncthreads();

    const int b = blockIdx.x * BLK + tid;
    const float4* xp = (const float4*)(x + (size_t)b * TSTEPS * INDIM);  // 7 float4 per step

    float c0 = 0, c1 = 0, c2 = 0, c3 = 0, c4 = 0, c5 = 0, c6 = 0, c7 = 0;
    // h packed into two float4 "segments" so the segment loop index never
    // touches an addressable array.
    float4 hA = make_float4(0, 0, 0, 0);   // h0..h3
    float4 hB = make_float4(0, 0, 0, 0);   // h4..h7

#pragma unroll 1
    for (int t = 0; t < TSTEPS; t++) {
        u64 g[16];
#pragma unroll
        for (int q = 0; q < 8; q++) {
            ulonglong2 bq = sB2[q];
            g[2 * q] = bq.x; g[2 * q + 1] = bq.y;
        }

        float4 cur = xp[t * 7];

        // 9 segments: 0..6 -> x chunks (rows 4s..4s+3), 7 -> hA (rows 28..31),
        // 8 -> hB (rows 32..35). unroll 1 = hard scheduling window boundary.
#pragma unroll 1
        for (int seg = 0; seg < 9; seg++) {
            float4 nxt;
            if (seg < 6)       nxt = xp[t * 7 + seg + 1];
            else if (seg == 6) nxt = hA;
            else if (seg == 7) nxt = hB;
            else               nxt = cur;   // dead

            const int krow = 4 * seg;
#pragma unroll
            for (int j = 0; j < 4; j++) {
                float xs = (j == 0) ? cur.x : (j == 1) ? cur.y : (j == 2) ? cur.z : cur.w;
                u64 xx = pack2(xs);
#pragma unroll
                for (int q = 0; q < 8; q++) {
                    ulonglong2 w = sW2[(krow + j) * 8 + q];
                    g[2 * q]     = fma2(xx, w.x, g[2 * q]);
                    g[2 * q + 1] = fma2(xx, w.y, g[2 * q + 1]);
                }
            }
            cur = nxt;
        }

        // activations: cols 0..7=i, 8..15=j, 16..23=f, 24..31=o.
        // pair p holds cols 2p,2p+1.
        float ia[8], ja[8], fa[8], oa[8];
#pragma unroll
        for (int v = 0; v < 4; v++) {
            unpack2(g[v],      ia[2 * v], ia[2 * v + 1]);
            unpack2(g[4 + v],  ja[2 * v], ja[2 * v + 1]);
            unpack2(g[8 + v],  fa[2 * v], fa[2 * v + 1]);
            unpack2(g[12 + v], oa[2 * v], oa[2 * v + 1]);
        }

        float hn[8];
        float ca[8] = {c0, c1, c2, c3, c4, c5, c6, c7};
#pragma unroll
        for (int u = 0; u < HID; u++) {
            float ig = sigf(ia[u]);
            float jt = tanh_exact(ja[u]);
            float fg = sigf(fa[u] + 1.0f);   // forget bias
            float og = sigf(oa[u]);
            float cn = ca[u] * fg + ig * jt;
            ca[u] = cn;
            hn[u] = tanh_exact(cn) * og;
        }
        c0 = ca[0]; c1 = ca[1]; c2 = ca[2]; c3 = ca[3];
        c4 = ca[4]; c5 = ca[5]; c6 = ca[6]; c7 = ca[7];
        hA = make_float4(hn[0], hn[1], hn[2], hn[3]);
        hB = make_float4(hn[4], hn[5], hn[6], hn[7]);
    }

    // Output projection: logits = h @ ow + ob
    float hf[8] = {hA.x, hA.y, hA.z, hA.w, hB.x, hB.y, hB.z, hB.w};
    float* op = out + (size_t)b * NCLS;
#pragma unroll
    for (int n = 0; n < NCLS; n++) {
        float acc = sOB[n];
#pragma unroll
        for (int u = 0; u < HID; u++) acc += hf[u] * sOW[u * NCLS + n];
        op[n] = acc;
    }
}

extern "C" void kernel_launch(void* const* d_in, const int* in_sizes, int n_in,
                              void* d_out, int out_size) {
    const float* x  = (const float*)d_in[0];
    const float* W  = (const float*)d_in[1];
    const float* bl = (const float*)d_in[2];
    const float* ow = (const float*)d_in[3];
    const float* ob = (const float*)d_in[4];
    float* out = (float*)d_out;

    lstm_kernel<<<BTOT / BLK, BLK>>>(x, W, bl, ow, ob, out);
}